// round 16
// baseline (speedup 1.0000x reference)
#include <cuda_runtime.h>
#include <cuda_fp16.h>
#include <cstdint>
#include <math.h>

#define N_ROWS 4096
#define HID 512
#define TSTEPS 12
#define KZX 256
#define G3 1536
#define LDW_IH 258
#define BKC 64                 // K (halves) per stage
#define STAGE_BYTES 32768      // A 16KB + B 16KB per stage
#define NSTAGE 3
#define DSMEM (NSTAGE * STAGE_BYTES)
#define GCAT 2048              // 512 (W_h0) + 1536 (W_ih[:, :256])

// ---------------- device scratch (no allocs allowed) ----------------
__device__ __half g_zx  [N_ROWS * KZX];  // concat(z,x), fp16
__device__ __half g_h   [N_ROWS * HID];  // hidden state, fp16
__device__ __half g_gi  [N_ROWS * G3];   // gi_zx (fp16, bias incl.)
__device__ __half g_gh  [N_ROWS * G3];   // gh per step (fp16, bias incl.)
__device__ float  g_x   [N_ROWS * 2];    // current action
__device__ __half g_wcat[GCAT * KZX];    // [W_h0; W_ih[:,:256]] fp16
__device__ float  g_bcat[GCAT];          // [b_h0; b_ih]
__device__ __half g_wh  [G3 * HID];      // W_hh, fp16
__device__ float  g_wt  [G3 * 2];        // W_ih[:, 256:258] packed (fp32)

// ---------------- helpers ----------------
__device__ __forceinline__ float rcp_fast(float v) {
    float r; asm("rcp.approx.f32 %0, %1;" : "=f"(r) : "f"(v));
    return r;
}
__device__ __forceinline__ uint32_t smem_u32(const void* p) {
    uint32_t a;
    asm("{ .reg .u64 t; cvta.to.shared.u64 t, %1; cvt.u32.u64 %0, t; }"
        : "=r"(a) : "l"(p));
    return a;
}
__device__ __forceinline__ void cp16(uint32_t dst, const void* src) {
    asm volatile("cp.async.cg.shared.global [%0], [%1], 16;" :: "r"(dst), "l"(src));
}
__device__ __forceinline__ void ldsm4(uint32_t addr, uint32_t& r0, uint32_t& r1,
                                      uint32_t& r2, uint32_t& r3) {
    asm volatile("ldmatrix.sync.aligned.m8n8.x4.shared.b16 {%0,%1,%2,%3}, [%4];"
                 : "=r"(r0), "=r"(r1), "=r"(r2), "=r"(r3) : "r"(addr));
}

// ---------------------------------------------------------------------------
// ONE prologue kernel: zx concat, a0, weight packs, bias concat.
// ---------------------------------------------------------------------------
#define PR_ZX   (N_ROWS * 128)                  // 524288
#define PR_A0   (PR_ZX + N_ROWS)                // + 4096
#define PR_WCAT (PR_A0 + GCAT * KZX)            // + 524288
#define PR_WH   (PR_WCAT + G3 * HID)            // + 786432
#define PR_WT   (PR_WH + G3 * 2)                // + 3072
#define PR_BCAT (PR_WT + GCAT)                  // + 2048
__global__ void prologue_kernel(const float* __restrict__ z,
                                const float* __restrict__ x,
                                const float* __restrict__ x0,
                                const float* __restrict__ W_ia,
                                const float* __restrict__ b_ia,
                                const float* __restrict__ W_h0,
                                const float* __restrict__ b_h0,
                                const float* __restrict__ W_ih,
                                const float* __restrict__ b_ih,
                                const float* __restrict__ W_hh) {
    int i = blockIdx.x * blockDim.x + threadIdx.x;
    if (i < PR_ZX) {
        int row = i >> 7, c = i & 127;
        g_zx[row * KZX + c]       = __float2half_rn(z[i]);
        g_zx[row * KZX + 128 + c] = __float2half_rn(x[i]);
    } else if (i < PR_A0) {
        int row = i - PR_ZX;
        float v0 = x0[row * 4 + 0], v1 = x0[row * 4 + 1];
        float v2 = x0[row * 4 + 2], v3 = x0[row * 4 + 3];
#pragma unroll
        for (int c = 0; c < 2; ++c) {
            g_x[row * 2 + c] = b_ia[c] + v0 * W_ia[c * 4 + 0] + v1 * W_ia[c * 4 + 1]
                                       + v2 * W_ia[c * 4 + 2] + v3 * W_ia[c * 4 + 3];
        }
    } else if (i < PR_WCAT) {
        int j = i - PR_A0;
        int r = j >> 8, c = j & 255;
        float v = (r < HID) ? W_h0[r * KZX + c]
                            : W_ih[(size_t)(r - HID) * LDW_IH + c];
        g_wcat[j] = __float2half_rn(v);
    } else if (i < PR_WH) {
        int j = i - PR_WCAT;
        g_wh[j] = __float2half_rn(W_hh[j]);
    } else if (i < PR_WT) {
        int j = i - PR_WH;
        int r = j >> 1, c = j & 1;
        g_wt[j] = W_ih[(size_t)r * LDW_IH + 256 + c];
    } else if (i < PR_BCAT) {
        int r = i - PR_WT;
        g_bcat[r] = (r < HID) ? b_h0[r] : b_ih[r - HID];
    }
}

// ---------------------------------------------------------------------------
// fp16 mma.sync GEMM (R15-proven core) with split-destination epilogue:
//   C[4096, M_out] = A[4096, K] @ W[M_out, K]^T + bias
// cols < splitcol -> C1 (ldc1); cols >= splitcol -> C2 at col-splitcol (ldc2).
// CTA 128x128, 4 warps (2x2), warp tile 64x64 m16n8k16, BK=64, 3-stage
// cp.async ring, XOR swizzle, ldmatrix.x4, double-buffered frags,
// one __syncthreads per stage with prefetch before compute.
// ---------------------------------------------------------------------------
__global__ __launch_bounds__(128, 2)
void sgemm_mma(const __half* __restrict__ A, int lda,
               const __half* __restrict__ W, int ldw,
               const float* __restrict__ bias,
               __half* __restrict__ C1, int ldc1,
               __half* __restrict__ C2, int ldc2,
               int splitcol, int K)
{
    extern __shared__ char smraw[];
    const int tid = threadIdx.x;
    const int wid = tid >> 5;
    const int lane = tid & 31;
    const int gid = lane >> 2;
    const int tig = lane & 3;
    const int warp_m = wid & 1;
    const int warp_n = wid >> 1;
    const int rowBase = blockIdx.y * 128;
    const int colBase = blockIdx.x * 128;
    const int NK = K / BKC;

    const uint32_t smBase = smem_u32(smraw);

    // ldmatrix per-lane geometry
    const int rl   = lane & 7;
    const int am8  = (lane >> 3) & 1;
    const int ksel = lane >> 4;
    uint32_t aRowB[4];
#pragma unroll
    for (int mt = 0; mt < 4; ++mt)
        aRowB[mt] = (uint32_t)((warp_m * 64 + mt * 16 + rl + am8 * 8) * 128);
    uint32_t bRowB[4];
#pragma unroll
    for (int g = 0; g < 4; ++g)
        bRowB[g] = (uint32_t)((warp_n * 64 + (2 * g + ksel) * 8 + rl) * 128);

    auto load_stage = [&](int ks, int slot) {
        const int k0 = ks * BKC;
        const uint32_t aOff = smBase + (uint32_t)slot * STAGE_BYTES;
        const uint32_t bOff = aOff + 16384u;
#pragma unroll
        for (int i = 0; i < 8; ++i) {
            int q = tid + i * 128;
            int r = q >> 3;
            int c = q & 7;
            uint32_t d = (uint32_t)(r * 128 + ((c ^ (r & 7)) << 4));
            cp16(aOff + d, A + (size_t)(rowBase + r) * lda + k0 + c * 8);
            cp16(bOff + d, W + (size_t)(colBase + r) * ldw + k0 + c * 8);
        }
        asm volatile("cp.async.commit_group;" ::: "memory");
    };

    float acc[4][8][4];
#pragma unroll
    for (int mt = 0; mt < 4; ++mt)
#pragma unroll
        for (int nt = 0; nt < 8; ++nt)
#pragma unroll
            for (int c = 0; c < 4; ++c) acc[mt][nt][c] = 0.f;

    uint32_t fa[2][4][4], fb[2][8][2];

    auto load_frags = [&](uint32_t aOff, uint32_t bOff, int kk, int buf) {
        const uint32_t cA = (uint32_t)(((2 * kk + ksel) ^ rl) << 4);
        const uint32_t cB = (uint32_t)(((2 * kk + am8) ^ rl) << 4);
#pragma unroll
        for (int mt = 0; mt < 4; ++mt)
            ldsm4(aOff + aRowB[mt] + cA,
                  fa[buf][mt][0], fa[buf][mt][1], fa[buf][mt][2], fa[buf][mt][3]);
#pragma unroll
        for (int g = 0; g < 4; ++g)
            ldsm4(bOff + bRowB[g] + cB,
                  fb[buf][2 * g][0], fb[buf][2 * g][1],
                  fb[buf][2 * g + 1][0], fb[buf][2 * g + 1][1]);
    };

    auto mma_all = [&](int buf) {
#pragma unroll
        for (int mt = 0; mt < 4; ++mt)
#pragma unroll
            for (int nt = 0; nt < 8; ++nt) {
                asm volatile(
                    "mma.sync.aligned.m16n8k16.row.col.f32.f16.f16.f32 "
                    "{%0,%1,%2,%3}, {%4,%5,%6,%7}, {%8,%9}, {%0,%1,%2,%3};"
                    : "+f"(acc[mt][nt][0]), "+f"(acc[mt][nt][1]),
                      "+f"(acc[mt][nt][2]), "+f"(acc[mt][nt][3])
                    : "r"(fa[buf][mt][0]), "r"(fa[buf][mt][1]),
                      "r"(fa[buf][mt][2]), "r"(fa[buf][mt][3]),
                      "r"(fb[buf][nt][0]), "r"(fb[buf][nt][1]));
            }
    };

    load_stage(0, 0);
    load_stage(1, 1);

    for (int ks = 0; ks < NK; ++ks) {
        if (ks + 1 < NK) {
            asm volatile("cp.async.wait_group 1;" ::: "memory");
        } else {
            asm volatile("cp.async.wait_group 0;" ::: "memory");
        }
        __syncthreads();   // data visible + prior buffer free

        if (ks + 2 < NK) load_stage(ks + 2, (ks + 2) % NSTAGE);

        const int slot = ks % NSTAGE;
        const uint32_t aOff = smBase + (uint32_t)slot * STAGE_BYTES;
        const uint32_t bOff = aOff + 16384u;

        load_frags(aOff, bOff, 0, 0);
#pragma unroll
        for (int kk = 0; kk < 4; ++kk) {
            if (kk < 3) load_frags(aOff, bOff, kk + 1, (kk + 1) & 1);
            mma_all(kk & 1);
        }
    }

    // split-destination epilogue (per-CTA uniform: colBase multiple of 128)
    __half* Cp; int ldcp, cOff;
    if (colBase < splitcol) { Cp = C1; ldcp = ldc1; cOff = colBase; }
    else                    { Cp = C2; ldcp = ldc2; cOff = colBase - splitcol; }

#pragma unroll
    for (int mt = 0; mt < 4; ++mt) {
        int row = rowBase + warp_m * 64 + mt * 16 + gid;
#pragma unroll
        for (int nt = 0; nt < 8; ++nt) {
            int lc = warp_n * 64 + nt * 8 + tig * 2;
            float b0 = bias[colBase + lc], b1 = bias[colBase + lc + 1];
            int col = cOff + lc;
            *reinterpret_cast<__half2*>(Cp + (size_t)row * ldcp + col) =
                __floats2half2_rn(acc[mt][nt][0] + b0, acc[mt][nt][1] + b1);
            *reinterpret_cast<__half2*>(Cp + (size_t)(row + 8) * ldcp + col) =
                __floats2half2_rn(acc[mt][nt][2] + b0, acc[mt][nt][3] + b1);
        }
    }
}

// ---------------------------------------------------------------------------
// Fused gate math + hidden update + output projection.
// 4 rows per 512-thread block; gi/gh fp16 (bias pre-folded).
// ---------------------------------------------------------------------------
__device__ __forceinline__ float fast_sigmoid(float x) {
    return rcp_fast(1.f + __expf(-x));
}
__device__ __forceinline__ float fast_tanh(float x) {
    float t = __expf(-2.f * fabsf(x));
    float m = (1.f - t) * rcp_fast(1.f + t);
    return copysignf(m, x);
}
__device__ __forceinline__ void ld_half4(const __half* p, float* dst) {
    uint2 raw = *reinterpret_cast<const uint2*>(p);
    float2 p0 = __half22float2(*reinterpret_cast<__half2*>(&raw.x));
    float2 p1 = __half22float2(*reinterpret_cast<__half2*>(&raw.y));
    dst[0] = p0.x; dst[1] = p0.y; dst[2] = p1.x; dst[3] = p1.y;
}

__global__ __launch_bounds__(512)
void gate_kernel(const float* __restrict__ W_out,
                 const float* __restrict__ b_out,
                 float* __restrict__ out, int t) {
    int tid = threadIdx.x;
    int row = blockIdx.x * 4 + (tid >> 7);
    int wt = tid & 127;
    float xa = g_x[row * 2 + 0];
    float xb = g_x[row * 2 + 1];

    int j0 = wt * 4;
    const __half* gi = &g_gi[(size_t)row * G3];
    const __half* gh = &g_gh[(size_t)row * G3];

    float gir[4], giz[4], gin[4], ghr[4], ghz[4], ghn[4], hv[4];
    ld_half4(gi + j0, gir);
    ld_half4(gi + 512 + j0, giz);
    ld_half4(gi + 1024 + j0, gin);
    ld_half4(gh + j0, ghr);
    ld_half4(gh + 512 + j0, ghz);
    ld_half4(gh + 1024 + j0, ghn);
    ld_half4(&g_h[(size_t)row * HID + j0], hv);

    float wr[8], wz[8], wn[8];
    *reinterpret_cast<float4*>(&wr[0]) = *reinterpret_cast<const float4*>(&g_wt[(size_t)j0 * 2]);
    *reinterpret_cast<float4*>(&wr[4]) = *reinterpret_cast<const float4*>(&g_wt[(size_t)j0 * 2 + 4]);
    *reinterpret_cast<float4*>(&wz[0]) = *reinterpret_cast<const float4*>(&g_wt[(size_t)(512 + j0) * 2]);
    *reinterpret_cast<float4*>(&wz[4]) = *reinterpret_cast<const float4*>(&g_wt[(size_t)(512 + j0) * 2 + 4]);
    *reinterpret_cast<float4*>(&wn[0]) = *reinterpret_cast<const float4*>(&g_wt[(size_t)(1024 + j0) * 2]);
    *reinterpret_cast<float4*>(&wn[4]) = *reinterpret_cast<const float4*>(&g_wt[(size_t)(1024 + j0) * 2 + 4]);

    float o0 = 0.f, o1 = 0.f;
    float hn[4];
#pragma unroll
    for (int i = 0; i < 4; ++i) {
        int j = j0 + i;
        float gi_r = gir[i] + xa * wr[i * 2] + xb * wr[i * 2 + 1];
        float gi_z = giz[i] + xa * wz[i * 2] + xb * wz[i * 2 + 1];
        float gi_n = gin[i] + xa * wn[i * 2] + xb * wn[i * 2 + 1];
        float r = fast_sigmoid(gi_r + ghr[i]);
        float u = fast_sigmoid(gi_z + ghz[i]);
        float n = fast_tanh(gi_n + r * ghn[i]);
        float h_new = (1.f - u) * n + u * hv[i];
        hn[i] = h_new;
        o0 += h_new * W_out[j];
        o1 += h_new * W_out[HID + j];
    }
    {
        __half2 p0 = __floats2half2_rn(hn[0], hn[1]);
        __half2 p1 = __floats2half2_rn(hn[2], hn[3]);
        uint2 hraw;
        hraw.x = *reinterpret_cast<uint32_t*>(&p0);
        hraw.y = *reinterpret_cast<uint32_t*>(&p1);
        *reinterpret_cast<uint2*>(&g_h[(size_t)row * HID + j0]) = hraw;
    }

    unsigned m = 0xffffffffu;
#pragma unroll
    for (int off = 16; off; off >>= 1) {
        o0 += __shfl_down_sync(m, o0, off);
        o1 += __shfl_down_sync(m, o1, off);
    }
    __shared__ float s0[16], s1[16];
    int wi = tid >> 5, lane = tid & 31;
    if (lane == 0) { s0[wi] = o0; s1[wi] = o1; }
    __syncthreads();
    if (wt == 0) {
        int base = (tid >> 7) * 4;
        float r0 = s0[base] + s0[base + 1] + s0[base + 2] + s0[base + 3] + b_out[0];
        float r1 = s1[base] + s1[base + 1] + s1[base + 2] + s1[base + 3] + b_out[1];
        out[row * (TSTEPS * 2) + t * 2 + 0] = r0;
        out[row * (TSTEPS * 2) + t * 2 + 1] = r1;
        g_x[row * 2 + 0] = r0;
        g_x[row * 2 + 1] = r1;
    }
}

// ---------------------------------------------------------------------------
// Host launcher
// ---------------------------------------------------------------------------
static void* sym_addr(const void* sym) {
    void* p = nullptr;
    cudaGetSymbolAddress(&p, sym);
    return p;
}

extern "C" void kernel_launch(void* const* d_in, const int* in_sizes, int n_in,
                              void* d_out, int out_size) {
    const float* z     = (const float*)d_in[0];
    const float* x     = (const float*)d_in[1];
    const float* x0    = (const float*)d_in[2];
    const float* W_ia  = (const float*)d_in[3];
    const float* b_ia  = (const float*)d_in[4];
    const float* W_h0  = (const float*)d_in[5];
    const float* b_h0  = (const float*)d_in[6];
    const float* W_ih  = (const float*)d_in[7];
    const float* b_ih  = (const float*)d_in[8];
    const float* W_hh  = (const float*)d_in[9];
    const float* b_hh  = (const float*)d_in[10];
    const float* W_out = (const float*)d_in[11];
    const float* b_out = (const float*)d_in[12];
    float* out = (float*)d_out;

    __half* p_zx   = (__half*)sym_addr(g_zx);
    __half* p_h    = (__half*)sym_addr(g_h);
    __half* p_gi   = (__half*)sym_addr(g_gi);
    __half* p_gh   = (__half*)sym_addr(g_gh);
    __half* p_wcat = (__half*)sym_addr(g_wcat);
    float*  p_bcat = (float*)sym_addr(g_bcat);
    __half* p_wh   = (__half*)sym_addr(g_wh);

    cudaFuncSetAttribute(sgemm_mma, cudaFuncAttributeMaxDynamicSharedMemorySize, DSMEM);

    // one prologue launch
    prologue_kernel<<<(PR_BCAT + 255) / 256, 256>>>(
        z, x, x0, W_ia, b_ia, W_h0, b_h0, W_ih, b_ih, W_hh);

    // cat GEMM: [h0 | gi] = zx @ [W_h0; W_ih[:,:256]].T + [b_h0; b_ih]
    sgemm_mma<<<dim3(GCAT / 128, N_ROWS / 128), 128, DSMEM>>>(
        p_zx, KZX, p_wcat, KZX, p_bcat,
        p_h, HID, p_gi, G3, HID, KZX);

    // recurrent steps (gh fp16, bias included)
    for (int t = 0; t < TSTEPS; ++t) {
        sgemm_mma<<<dim3(G3 / 128, N_ROWS / 128), 128, DSMEM>>>(
            p_h, HID, p_wh, HID, b_hh,
            p_gh, G3, p_gh, G3, 0, HID);
        gate_kernel<<<N_ROWS / 4, 512>>>(W_out, b_out, out, t);
    }
}